// round 10
// baseline (speedup 1.0000x reference)
#include <cuda_runtime.h>
#include <cuda_fp16.h>
#include <cstdint>
#include <math.h>

#define H_DIM 128
#define R_DIM 6
#define D_DIM 256
#define MAX_NODES 50000

// Scratch
__device__ __align__(128) float g_agg[(size_t)MAX_NODES * H_DIM];   // 25.6 MB
__device__ __align__(128) float g_y0 [(size_t)MAX_NODES * D_DIM];   // 51.2 MB
__device__ __align__(128) float g_y1 [(size_t)MAX_NODES * D_DIM];   // 51.2 MB
// Pre-split weights (fp16 hi/lo): [0,32768) = W_up (256x128), then 3x Ws (256x256)
#define W_TOTAL (256*128 + 3*256*256)
__device__ __align__(128) __half g_whi[W_TOTAL];
__device__ __align__(128) __half g_wlo[W_TOTAL];

__device__ __forceinline__ uint32_t pack_h2(float a, float b) {
    __half2 v = __halves2half2(__float2half_rn(a), __float2half_rn(b));
    return *reinterpret_cast<uint32_t*>(&v);
}

// ---------------------------------------------------------------------------
// Prep kernels
// ---------------------------------------------------------------------------
__global__ void prep_w(const float* __restrict__ W_up, const float* __restrict__ Ws,
                       __half* __restrict__ whi, __half* __restrict__ wlo) {
    int i = blockIdx.x * blockDim.x + threadIdx.x;
    int stride = gridDim.x * blockDim.x;
    for (; i < W_TOTAL; i += stride) {
        float v = (i < 256 * 128) ? W_up[i] : Ws[i - 256 * 128];
        __half h = __float2half_rn(v);
        whi[i] = h;
        wlo[i] = __float2half_rn(v - __half2float(h));
    }
}

__global__ void zero_kernel(float4* __restrict__ p, int n4) {
    int i = blockIdx.x * blockDim.x + threadIdx.x;
    int stride = gridDim.x * blockDim.x;
    float4 z = make_float4(0.f, 0.f, 0.f, 0.f);
    for (; i < n4; i += stride) p[i] = z;
}

// ---------------------------------------------------------------------------
// Edge stage (round-5 proven best: 2 edges/warp-iter, 4ch/lane, red.v4)
// ---------------------------------------------------------------------------
__global__ void edge_kernel(const float* __restrict__ x,
                            const float* __restrict__ rbf,
                            const int*   __restrict__ idx,
                            const float* __restrict__ Wrbf,
                            float*       __restrict__ agg,
                            int E) {
    const int lane = threadIdx.x & 31;
    const int warp = (blockIdx.x * blockDim.x + threadIdx.x) >> 5;
    const int nwarps = (gridDim.x * blockDim.x) >> 5;

    float w[4][6];
    #pragma unroll
    for (int j = 0; j < 4; ++j)
        #pragma unroll
        for (int r = 0; r < R_DIM; ++r)
            w[j][r] = __ldg(Wrbf + (lane * 4 + j) * R_DIM + r);

    for (int e0 = warp * 2; e0 < E; e0 += nwarps * 2) {
        const int e1 = e0 + 1;
        const bool has1 = e1 < E;

        const float2* rp0 = reinterpret_cast<const float2*>(rbf + (size_t)e0 * R_DIM);
        float2 a01 = __ldg(rp0 + 0), a23 = __ldg(rp0 + 1), a45 = __ldg(rp0 + 2);
        int n0 = __ldg(idx + e0);
        float4 xv0 = __ldg(reinterpret_cast<const float4*>(x + (size_t)e0 * H_DIM) + lane);

        float2 b01 = a01, b23 = a23, b45 = a45;
        int n1 = n0;
        float4 xv1 = make_float4(0.f, 0.f, 0.f, 0.f);
        if (has1) {
            const float2* rp1 = reinterpret_cast<const float2*>(rbf + (size_t)e1 * R_DIM);
            b01 = __ldg(rp1 + 0); b23 = __ldg(rp1 + 1); b45 = __ldg(rp1 + 2);
            n1 = __ldg(idx + e1);
            xv1 = __ldg(reinterpret_cast<const float4*>(x + (size_t)e1 * H_DIM) + lane);
        }

        #pragma unroll
        for (int pass = 0; pass < 2; ++pass) {
            float2 r01 = pass ? b01 : a01;
            float2 r23 = pass ? b23 : a23;
            float2 r45 = pass ? b45 : a45;
            float4 xv  = pass ? xv1 : xv0;
            int node   = pass ? n1 : n0;
            if (pass && !has1) break;

            float g0 = w[0][0]*r01.x + w[0][1]*r01.y + w[0][2]*r23.x + w[0][3]*r23.y + w[0][4]*r45.x + w[0][5]*r45.y;
            float g1 = w[1][0]*r01.x + w[1][1]*r01.y + w[1][2]*r23.x + w[1][3]*r23.y + w[1][4]*r45.x + w[1][5]*r45.y;
            float g2 = w[2][0]*r01.x + w[2][1]*r01.y + w[2][2]*r23.x + w[2][3]*r23.y + w[2][4]*r45.x + w[2][5]*r45.y;
            float g3 = w[3][0]*r01.x + w[3][1]*r01.y + w[3][2]*r23.x + w[3][3]*r23.y + w[3][4]*r45.x + w[3][5]*r45.y;

            float vx = g0 * xv.x, vy = g1 * xv.y, vz = g2 * xv.z, vw = g3 * xv.w;
            float* dst = agg + (size_t)node * H_DIM + lane * 4;
            asm volatile("red.global.add.v4.f32 [%0], {%1, %2, %3, %4};"
                         :: "l"(dst), "f"(vx), "f"(vy), "f"(vz), "f"(vw) : "memory");
        }
    }
}

// ---------------------------------------------------------------------------
// fp16-split GEMM: D = act(A @ B^T + bias)
//   hi*hi  -> mma f32 accum
//   hi*lo, lo*hi -> mma f16 accum (values ~2^-11 of result; f16 acc safe)
// CTA tile 128(m) x 128(n), 8 warps of 32x64, K chunks of 32.
// Two-pass inner loop (ahi pass, alo pass) to bound register liveness.
// ---------------------------------------------------------------------------
#define STRIDE_H 40   // halfwords per SMEM row (32 data + 8 pad)

__device__ __forceinline__ void mma_f32acc(float* d, const uint32_t* a, uint32_t b0, uint32_t b1) {
    asm("mma.sync.aligned.m16n8k16.row.col.f32.f16.f16.f32 "
        "{%0,%1,%2,%3}, {%4,%5,%6,%7}, {%8,%9}, {%0,%1,%2,%3};"
        : "+f"(d[0]), "+f"(d[1]), "+f"(d[2]), "+f"(d[3])
        : "r"(a[0]), "r"(a[1]), "r"(a[2]), "r"(a[3]), "r"(b0), "r"(b1));
}
__device__ __forceinline__ void mma_f16acc(uint32_t* d, const uint32_t* a, uint32_t b0, uint32_t b1) {
    asm("mma.sync.aligned.m16n8k16.row.col.f16.f16.f16.f16 "
        "{%0,%1}, {%2,%3,%4,%5}, {%6,%7}, {%0,%1};"
        : "+r"(d[0]), "+r"(d[1])
        : "r"(a[0]), "r"(a[1]), "r"(a[2]), "r"(a[3]), "r"(b0), "r"(b1));
}

template<int K_TOTAL, bool BIAS, bool SILU, bool PROJ>
__global__ void __launch_bounds__(256, 2)
gemm_mma(const float* __restrict__ A,
         const __half* __restrict__ Bhi,
         const __half* __restrict__ Blo,
         const float* __restrict__ bias,
         const float* __restrict__ wout,
         float* __restrict__ Y,
         int M) {
    __shared__ __align__(16) uint16_t sAhi[128 * STRIDE_H];
    __shared__ __align__(16) uint16_t sAlo[128 * STRIDE_H];
    __shared__ __align__(16) uint16_t sBhi[128 * STRIDE_H];
    __shared__ __align__(16) uint16_t sBlo[128 * STRIDE_H];

    const int tid  = threadIdx.x;
    const int wid  = tid >> 5, lane = tid & 31;
    const int g    = lane >> 2, t = lane & 3;
    const int m0   = blockIdx.x * 128;
    const int n0   = blockIdx.y * 128;
    const int wm   = (wid & 3) * 32;
    const int wn   = (wid >> 2) * 64;

    float    accH[2][8][4];     // hi*hi, fp32
    uint32_t accX[2][8][2];     // cross terms, fp16x2
    #pragma unroll
    for (int i = 0; i < 2; ++i)
        #pragma unroll
        for (int j = 0; j < 8; ++j) {
            #pragma unroll
            for (int q = 0; q < 4; ++q) accH[i][j][q] = 0.f;
            accX[i][j][0] = 0u; accX[i][j][1] = 0u;
        }

    const uint32_t* A32hi = reinterpret_cast<const uint32_t*>(sAhi);
    const uint32_t* A32lo = reinterpret_cast<const uint32_t*>(sAlo);
    const uint32_t* B32hi = reinterpret_cast<const uint32_t*>(sBhi);
    const uint32_t* B32lo = reinterpret_cast<const uint32_t*>(sBlo);

    const int fr = tid >> 1;
    const int fh = tid & 1;
    const bool a_valid = (m0 + fr) < M;

    for (int c = 0; c < K_TOTAL / 32; ++c) {
        // ---- fill A (fp32 -> fp16 hi/lo) ----
        {
            const float* ap = A + (size_t)(m0 + fr) * K_TOTAL + c * 32 + fh * 16;
            #pragma unroll
            for (int q4 = 0; q4 < 2; ++q4) {
                float4 f0 = make_float4(0.f,0.f,0.f,0.f), f1 = f0;
                if (a_valid) {
                    f0 = *reinterpret_cast<const float4*>(ap + q4 * 8);
                    f1 = *reinterpret_cast<const float4*>(ap + q4 * 8 + 4);
                }
                uint4 Hv, Lv;
                Hv.x = pack_h2(f0.x, f0.y); Hv.y = pack_h2(f0.z, f0.w);
                Hv.z = pack_h2(f1.x, f1.y); Hv.w = pack_h2(f1.z, f1.w);
                float e0 = f0.x - __half2float(__float2half_rn(f0.x));
                float e1 = f0.y - __half2float(__float2half_rn(f0.y));
                float e2 = f0.z - __half2float(__float2half_rn(f0.z));
                float e3 = f0.w - __half2float(__float2half_rn(f0.w));
                float e4 = f1.x - __half2float(__float2half_rn(f1.x));
                float e5 = f1.y - __half2float(__float2half_rn(f1.y));
                float e6 = f1.z - __half2float(__float2half_rn(f1.z));
                float e7 = f1.w - __half2float(__float2half_rn(f1.w));
                Lv.x = pack_h2(e0, e1); Lv.y = pack_h2(e2, e3);
                Lv.z = pack_h2(e4, e5); Lv.w = pack_h2(e6, e7);
                int hw = fr * STRIDE_H + fh * 16 + q4 * 8;
                *reinterpret_cast<uint4*>(sAhi + hw) = Hv;
                *reinterpret_cast<uint4*>(sAlo + hw) = Lv;
            }
        }
        // ---- fill B ----
        {
            const size_t boff = (size_t)(n0 + fr) * K_TOTAL + c * 32 + fh * 16;
            const uint4* bh = reinterpret_cast<const uint4*>(Bhi + boff);
            const uint4* bl = reinterpret_cast<const uint4*>(Blo + boff);
            int hw = fr * STRIDE_H + fh * 16;
            *reinterpret_cast<uint4*>(sBhi + hw)     = bh[0];
            *reinterpret_cast<uint4*>(sBhi + hw + 8) = bh[1];
            *reinterpret_cast<uint4*>(sBlo + hw)     = bl[0];
            *reinterpret_cast<uint4*>(sBlo + hw + 8) = bl[1];
        }
        __syncthreads();

        // ---- compute: per ks, two passes to bound register liveness ----
        #pragma unroll
        for (int ks = 0; ks < 2; ++ks) {
            const int kw = ks * 8;
            // pass 1: ahi -> hi*hi (f32 acc) + hi*lo (f16 acc)
            {
                uint32_t ahi[2][4];
                #pragma unroll
                for (int i = 0; i < 2; ++i) {
                    int r0 = (wm + i * 16 + g) * (STRIDE_H / 2) + kw + t;
                    ahi[i][0] = A32hi[r0];      ahi[i][1] = A32hi[r0 + 160];
                    ahi[i][2] = A32hi[r0 + 4];  ahi[i][3] = A32hi[r0 + 164];
                }
                #pragma unroll
                for (int j = 0; j < 8; ++j) {
                    int nb = (wn + j * 8 + g) * (STRIDE_H / 2) + kw + t;
                    uint32_t bh0 = B32hi[nb], bh1 = B32hi[nb + 4];
                    uint32_t bl0 = B32lo[nb], bl1 = B32lo[nb + 4];
                    #pragma unroll
                    for (int i = 0; i < 2; ++i) {
                        mma_f32acc(accH[i][j], ahi[i], bh0, bh1);
                        mma_f16acc(accX[i][j], ahi[i], bl0, bl1);
                    }
                }
            }
            // pass 2: alo -> lo*hi (f16 acc)
            {
                uint32_t alo[2][4];
                #pragma unroll
                for (int i = 0; i < 2; ++i) {
                    int r0 = (wm + i * 16 + g) * (STRIDE_H / 2) + kw + t;
                    alo[i][0] = A32lo[r0];      alo[i][1] = A32lo[r0 + 160];
                    alo[i][2] = A32lo[r0 + 4];  alo[i][3] = A32lo[r0 + 164];
                }
                #pragma unroll
                for (int j = 0; j < 8; ++j) {
                    int nb = (wn + j * 8 + g) * (STRIDE_H / 2) + kw + t;
                    uint32_t bh0 = B32hi[nb], bh1 = B32hi[nb + 4];
                    #pragma unroll
                    for (int i = 0; i < 2; ++i)
                        mma_f16acc(accX[i][j], alo[i], bh0, bh1);
                }
            }
        }
        __syncthreads();
    }

    // ---- epilogue ----
    if (PROJ) {
        float s[4] = {0.f, 0.f, 0.f, 0.f};
        #pragma unroll
        for (int i = 0; i < 2; ++i)
            #pragma unroll
            for (int j = 0; j < 8; ++j) {
                int col = n0 + wn + j * 8 + t * 2;
                float w0 = __ldg(wout + col), w1 = __ldg(wout + col + 1);
                float b0 = BIAS ? __ldg(bias + col) : 0.f;
                float b1 = BIAS ? __ldg(bias + col + 1) : 0.f;
                __half2 x0 = *reinterpret_cast<__half2*>(&accX[i][j][0]);
                __half2 x1 = *reinterpret_cast<__half2*>(&accX[i][j][1]);
                float v0 = accH[i][j][0] + __low2float(x0)  + b0;
                float v1 = accH[i][j][1] + __high2float(x0) + b1;
                float v2 = accH[i][j][2] + __low2float(x1)  + b0;
                float v3 = accH[i][j][3] + __high2float(x1) + b1;
                if (SILU) {
                    v0 = v0 / (1.f + __expf(-v0)); v1 = v1 / (1.f + __expf(-v1));
                    v2 = v2 / (1.f + __expf(-v2)); v3 = v3 / (1.f + __expf(-v3));
                }
                s[i * 2 + 0] += v0 * w0 + v1 * w1;
                s[i * 2 + 1] += v2 * w0 + v3 * w1;
            }
        #pragma unroll
        for (int q = 0; q < 4; ++q) {
            s[q] += __shfl_xor_sync(0xffffffffu, s[q], 1);
            s[q] += __shfl_xor_sync(0xffffffffu, s[q], 2);
        }
        if (t == 0) {
            #pragma unroll
            for (int i = 0; i < 2; ++i) {
                int r0 = m0 + wm + i * 16 + g;
                if (r0 < M)
                    asm volatile("red.global.add.f32 [%0], %1;" :: "l"(Y + r0), "f"(s[i*2]) : "memory");
                if (r0 + 8 < M)
                    asm volatile("red.global.add.f32 [%0], %1;" :: "l"(Y + r0 + 8), "f"(s[i*2+1]) : "memory");
            }
        }
    } else {
        #pragma unroll
        for (int i = 0; i < 2; ++i) {
            int r0 = m0 + wm + i * 16 + g;
            #pragma unroll
            for (int j = 0; j < 8; ++j) {
                int col = n0 + wn + j * 8 + t * 2;
                float b0 = BIAS ? __ldg(bias + col) : 0.f;
                float b1 = BIAS ? __ldg(bias + col + 1) : 0.f;
                __half2 x0 = *reinterpret_cast<__half2*>(&accX[i][j][0]);
                __half2 x1 = *reinterpret_cast<__half2*>(&accX[i][j][1]);
                float v0 = accH[i][j][0] + __low2float(x0)  + b0;
                float v1 = accH[i][j][1] + __high2float(x0) + b1;
                float v2 = accH[i][j][2] + __low2float(x1)  + b0;
                float v3 = accH[i][j][3] + __high2float(x1) + b1;
                if (SILU) {
                    v0 = v0 / (1.f + __expf(-v0)); v1 = v1 / (1.f + __expf(-v1));
                    v2 = v2 / (1.f + __expf(-v2)); v3 = v3 / (1.f + __expf(-v3));
                }
                if (r0 < M)
                    *reinterpret_cast<float2*>(Y + (size_t)r0 * D_DIM + col) = make_float2(v0, v1);
                if (r0 + 8 < M)
                    *reinterpret_cast<float2*>(Y + (size_t)(r0 + 8) * D_DIM + col) = make_float2(v2, v3);
            }
        }
    }
}

// ---------------------------------------------------------------------------
// Launch
// Inputs: 0:x[E,128] 1:rbf[E,6] 2:i[E] 3:W_rbf[128,6] 4:W_up[256,128]
//         5:Ws[3,256,256] 6:bs[3,256] 7:W_out[1,256] (8:num_nodes)
// ---------------------------------------------------------------------------
extern "C" void kernel_launch(void* const* d_in, const int* in_sizes, int n_in,
                              void* d_out, int out_size) {
    const float* x     = (const float*)d_in[0];
    const float* rbf   = (const float*)d_in[1];
    const int*   idx   = (const int*)  d_in[2];
    const float* W_rbf = (const float*)d_in[3];
    const float* W_up  = (const float*)d_in[4];
    const float* Ws    = (const float*)d_in[5];
    const float* bs    = (const float*)d_in[6];
    const float* W_out = (const float*)d_in[7];
    float* out = (float*)d_out;

    const int E = in_sizes[2];
    const int M = out_size;

    float *agg, *y0, *y1;
    __half *whi, *wlo;
    cudaGetSymbolAddress((void**)&agg, g_agg);
    cudaGetSymbolAddress((void**)&y0,  g_y0);
    cudaGetSymbolAddress((void**)&y1,  g_y1);
    cudaGetSymbolAddress((void**)&whi, g_whi);
    cudaGetSymbolAddress((void**)&wlo, g_wlo);

    prep_w<<<224, 256>>>(W_up, Ws, whi, wlo);
    zero_kernel<<<1024, 256>>>((float4*)agg, M * H_DIM / 4);
    zero_kernel<<<128, 256>>>((float4*)out, M / 4);

    edge_kernel<<<1184, 256>>>(x, rbf, idx, W_rbf, agg, E);

    const int tiles = (M + 127) / 128;
    dim3 grid(tiles, 2);
    const __half* whi_l = whi + 256 * 128;
    const __half* wlo_l = wlo + 256 * 128;

    // up-projection: y0 = agg @ W_up^T
    gemm_mma<128, false, false, false><<<grid, 256>>>(agg, whi, wlo, nullptr, nullptr, y0, M);
    // layer 0: y1 = silu(y0 @ W0^T + b0)
    gemm_mma<256, true, true, false><<<grid, 256>>>(y0, whi_l + 0*65536, wlo_l + 0*65536, bs + 0*D_DIM, nullptr, y1, M);
    // layer 1: y0 = silu(y1 @ W1^T + b1)
    gemm_mma<256, true, true, false><<<grid, 256>>>(y1, whi_l + 1*65536, wlo_l + 1*65536, bs + 1*D_DIM, nullptr, y0, M);
    // layer 2 + fused projection into out
    gemm_mma<256, true, true, true ><<<grid, 256>>>(y0, whi_l + 2*65536, wlo_l + 2*65536, bs + 2*D_DIM, W_out, out, M);
}

// round 11
// speedup vs baseline: 1.1130x; 1.1130x over previous
#include <cuda_runtime.h>
#include <cuda_fp16.h>
#include <cstdint>
#include <math.h>

#define H_DIM 128
#define R_DIM 6
#define D_DIM 256
#define MAX_NODES 50000

// Scratch
__device__ __align__(128) float g_agg[(size_t)MAX_NODES * H_DIM];   // 25.6 MB
__device__ __align__(128) float g_y0 [(size_t)MAX_NODES * D_DIM];   // 51.2 MB
__device__ __align__(128) float g_y1 [(size_t)MAX_NODES * D_DIM];   // 51.2 MB
// Pre-split weights (fp16 hi/lo): [0,32768) = W_up (256x128), then 3x Ws (256x256)
#define W_TOTAL (256*128 + 3*256*256)
__device__ __align__(128) __half g_whi[W_TOTAL];
__device__ __align__(128) __half g_wlo[W_TOTAL];

__device__ __forceinline__ uint32_t pack_h2(float a, float b) {
    __half2 v = __halves2half2(__float2half_rn(a), __float2half_rn(b));
    return *reinterpret_cast<uint32_t*>(&v);
}

// ---------------------------------------------------------------------------
// Prep kernels
// ---------------------------------------------------------------------------
__global__ void prep_w(const float* __restrict__ W_up, const float* __restrict__ Ws,
                       __half* __restrict__ whi, __half* __restrict__ wlo) {
    int i = blockIdx.x * blockDim.x + threadIdx.x;
    int stride = gridDim.x * blockDim.x;
    for (; i < W_TOTAL; i += stride) {
        float v = (i < 256 * 128) ? W_up[i] : Ws[i - 256 * 128];
        __half h = __float2half_rn(v);
        whi[i] = h;
        wlo[i] = __float2half_rn(v - __half2float(h));
    }
}

__global__ void zero_kernel(float4* __restrict__ p, int n4) {
    int i = blockIdx.x * blockDim.x + threadIdx.x;
    int stride = gridDim.x * blockDim.x;
    float4 z = make_float4(0.f, 0.f, 0.f, 0.f);
    for (; i < n4; i += stride) p[i] = z;
}

// ---------------------------------------------------------------------------
// Edge stage (round-5 proven best: 2 edges/warp-iter, 4ch/lane, red.v4)
// ---------------------------------------------------------------------------
__global__ void edge_kernel(const float* __restrict__ x,
                            const float* __restrict__ rbf,
                            const int*   __restrict__ idx,
                            const float* __restrict__ Wrbf,
                            float*       __restrict__ agg,
                            int E) {
    const int lane = threadIdx.x & 31;
    const int warp = (blockIdx.x * blockDim.x + threadIdx.x) >> 5;
    const int nwarps = (gridDim.x * blockDim.x) >> 5;

    float w[4][6];
    #pragma unroll
    for (int j = 0; j < 4; ++j)
        #pragma unroll
        for (int r = 0; r < R_DIM; ++r)
            w[j][r] = __ldg(Wrbf + (lane * 4 + j) * R_DIM + r);

    for (int e0 = warp * 2; e0 < E; e0 += nwarps * 2) {
        const int e1 = e0 + 1;
        const bool has1 = e1 < E;

        const float2* rp0 = reinterpret_cast<const float2*>(rbf + (size_t)e0 * R_DIM);
        float2 a01 = __ldg(rp0 + 0), a23 = __ldg(rp0 + 1), a45 = __ldg(rp0 + 2);
        int n0 = __ldg(idx + e0);
        float4 xv0 = __ldg(reinterpret_cast<const float4*>(x + (size_t)e0 * H_DIM) + lane);

        float2 b01 = a01, b23 = a23, b45 = a45;
        int n1 = n0;
        float4 xv1 = make_float4(0.f, 0.f, 0.f, 0.f);
        if (has1) {
            const float2* rp1 = reinterpret_cast<const float2*>(rbf + (size_t)e1 * R_DIM);
            b01 = __ldg(rp1 + 0); b23 = __ldg(rp1 + 1); b45 = __ldg(rp1 + 2);
            n1 = __ldg(idx + e1);
            xv1 = __ldg(reinterpret_cast<const float4*>(x + (size_t)e1 * H_DIM) + lane);
        }

        #pragma unroll
        for (int pass = 0; pass < 2; ++pass) {
            float2 r01 = pass ? b01 : a01;
            float2 r23 = pass ? b23 : a23;
            float2 r45 = pass ? b45 : a45;
            float4 xv  = pass ? xv1 : xv0;
            int node   = pass ? n1 : n0;
            if (pass && !has1) break;

            float g0 = w[0][0]*r01.x + w[0][1]*r01.y + w[0][2]*r23.x + w[0][3]*r23.y + w[0][4]*r45.x + w[0][5]*r45.y;
            float g1 = w[1][0]*r01.x + w[1][1]*r01.y + w[1][2]*r23.x + w[1][3]*r23.y + w[1][4]*r45.x + w[1][5]*r45.y;
            float g2 = w[2][0]*r01.x + w[2][1]*r01.y + w[2][2]*r23.x + w[2][3]*r23.y + w[2][4]*r45.x + w[2][5]*r45.y;
            float g3 = w[3][0]*r01.x + w[3][1]*r01.y + w[3][2]*r23.x + w[3][3]*r23.y + w[3][4]*r45.x + w[3][5]*r45.y;

            float vx = g0 * xv.x, vy = g1 * xv.y, vz = g2 * xv.z, vw = g3 * xv.w;
            float* dst = agg + (size_t)node * H_DIM + lane * 4;
            asm volatile("red.global.add.v4.f32 [%0], {%1, %2, %3, %4};"
                         :: "l"(dst), "f"(vx), "f"(vy), "f"(vz), "f"(vw) : "memory");
        }
    }
}

// ---------------------------------------------------------------------------
// fp16-split GEMM (3 products, all f32 acc) with COALESCED fills.
// CTA tile 128(m) x 128(n), 8 warps of 32x64, K chunks of 32.
// A fill: 8 threads/row (1 float4 each, 4 passes)  -> warp LDG spans 4 lines.
// B fill: 4 threads/row (1 uint4 each, 2 passes)   -> warp LDG spans 8 lines.
// ---------------------------------------------------------------------------
#define STRIDE_H 40   // halfwords per SMEM row (32 data + 8 pad)

__device__ __forceinline__ void mma_f16(float* d, const uint32_t* a, uint32_t b0, uint32_t b1) {
    asm("mma.sync.aligned.m16n8k16.row.col.f32.f16.f16.f32 "
        "{%0,%1,%2,%3}, {%4,%5,%6,%7}, {%8,%9}, {%0,%1,%2,%3};"
        : "+f"(d[0]), "+f"(d[1]), "+f"(d[2]), "+f"(d[3])
        : "r"(a[0]), "r"(a[1]), "r"(a[2]), "r"(a[3]), "r"(b0), "r"(b1));
}

template<int K_TOTAL, bool BIAS, bool SILU, bool PROJ>
__global__ void __launch_bounds__(256, 2)
gemm_mma(const float* __restrict__ A,
         const __half* __restrict__ Bhi,
         const __half* __restrict__ Blo,
         const float* __restrict__ bias,
         const float* __restrict__ wout,
         float* __restrict__ Y,
         int M) {
    __shared__ __align__(16) uint16_t sAhi[128 * STRIDE_H];
    __shared__ __align__(16) uint16_t sAlo[128 * STRIDE_H];
    __shared__ __align__(16) uint16_t sBhi[128 * STRIDE_H];
    __shared__ __align__(16) uint16_t sBlo[128 * STRIDE_H];

    const int tid  = threadIdx.x;
    const int wid  = tid >> 5, lane = tid & 31;
    const int g    = lane >> 2, t = lane & 3;
    const int m0   = blockIdx.x * 128;
    const int n0   = blockIdx.y * 128;
    const int wm   = (wid & 3) * 32;
    const int wn   = (wid >> 2) * 64;

    float acc[2][8][4];
    #pragma unroll
    for (int i = 0; i < 2; ++i)
        #pragma unroll
        for (int j = 0; j < 8; ++j)
            #pragma unroll
            for (int q = 0; q < 4; ++q) acc[i][j][q] = 0.f;

    const uint32_t* A32hi = reinterpret_cast<const uint32_t*>(sAhi);
    const uint32_t* A32lo = reinterpret_cast<const uint32_t*>(sAlo);
    const uint32_t* B32hi = reinterpret_cast<const uint32_t*>(sBhi);
    const uint32_t* B32lo = reinterpret_cast<const uint32_t*>(sBlo);

    // A fill addressing: 8 threads/row
    const int a_seg = tid & 7;         // float4 index within the 32-float slice
    const int a_rip = tid >> 3;        // row-in-pass (0..31)
    // B fill addressing: 4 threads/row
    const int b_seg = tid & 3;         // uint4 (8 halves) index within 32-half slice
    const int b_rip = tid >> 2;        // row-in-pass (0..63)

    for (int c = 0; c < K_TOTAL / 32; ++c) {
        // ---- fill A (coalesced: warp covers 4 rows x 128B lines) ----
        #pragma unroll
        for (int p = 0; p < 4; ++p) {
            const int row = p * 32 + a_rip;
            const int grow = m0 + row;
            float4 f = make_float4(0.f, 0.f, 0.f, 0.f);
            if (grow < M)
                f = *reinterpret_cast<const float4*>(A + (size_t)grow * K_TOTAL + c * 32 + a_seg * 4);
            uint2 Hv, Lv;
            Hv.x = pack_h2(f.x, f.y);
            Hv.y = pack_h2(f.z, f.w);
            Lv.x = pack_h2(f.x - __half2float(__float2half_rn(f.x)),
                           f.y - __half2float(__float2half_rn(f.y)));
            Lv.y = pack_h2(f.z - __half2float(__float2half_rn(f.z)),
                           f.w - __half2float(__float2half_rn(f.w)));
            const int hw = row * STRIDE_H + a_seg * 4;
            *reinterpret_cast<uint2*>(sAhi + hw) = Hv;
            *reinterpret_cast<uint2*>(sAlo + hw) = Lv;
        }
        // ---- fill B (coalesced: warp covers 8 rows x 64B slices) ----
        #pragma unroll
        for (int p = 0; p < 2; ++p) {
            const int row = p * 64 + b_rip;
            const size_t off = (size_t)(n0 + row) * K_TOTAL + c * 32 + b_seg * 8;
            uint4 bh = *reinterpret_cast<const uint4*>(Bhi + off);
            uint4 bl = *reinterpret_cast<const uint4*>(Blo + off);
            const int hw = row * STRIDE_H + b_seg * 8;
            *reinterpret_cast<uint4*>(sBhi + hw) = bh;
            *reinterpret_cast<uint4*>(sBlo + hw) = bl;
        }
        __syncthreads();

        // ---- compute: 3 products, f32 acc ----
        #pragma unroll
        for (int ks = 0; ks < 2; ++ks) {
            const int kw = ks * 8;
            uint32_t ahi[2][4], alo[2][4];
            #pragma unroll
            for (int i = 0; i < 2; ++i) {
                int r0 = (wm + i * 16 + g) * (STRIDE_H / 2) + kw + t;
                ahi[i][0] = A32hi[r0];        ahi[i][1] = A32hi[r0 + 160];
                ahi[i][2] = A32hi[r0 + 4];    ahi[i][3] = A32hi[r0 + 164];
                alo[i][0] = A32lo[r0];        alo[i][1] = A32lo[r0 + 160];
                alo[i][2] = A32lo[r0 + 4];    alo[i][3] = A32lo[r0 + 164];
            }
            #pragma unroll
            for (int j = 0; j < 8; ++j) {
                int nb = (wn + j * 8 + g) * (STRIDE_H / 2) + kw + t;
                uint32_t bh0 = B32hi[nb], bh1 = B32hi[nb + 4];
                uint32_t bl0 = B32lo[nb], bl1 = B32lo[nb + 4];
                #pragma unroll
                for (int i = 0; i < 2; ++i) {
                    mma_f16(acc[i][j], ahi[i], bh0, bh1);
                    mma_f16(acc[i][j], ahi[i], bl0, bl1);
                    mma_f16(acc[i][j], alo[i], bh0, bh1);
                }
            }
        }
        __syncthreads();
    }

    // ---- epilogue ----
    if (PROJ) {
        float s[4] = {0.f, 0.f, 0.f, 0.f};
        #pragma unroll
        for (int i = 0; i < 2; ++i)
            #pragma unroll
            for (int j = 0; j < 8; ++j) {
                int col = n0 + wn + j * 8 + t * 2;
                float w0 = __ldg(wout + col), w1 = __ldg(wout + col + 1);
                float b0 = BIAS ? __ldg(bias + col) : 0.f;
                float b1 = BIAS ? __ldg(bias + col + 1) : 0.f;
                float v0 = acc[i][j][0] + b0, v1 = acc[i][j][1] + b1;
                float v2 = acc[i][j][2] + b0, v3 = acc[i][j][3] + b1;
                if (SILU) {
                    v0 = v0 / (1.f + __expf(-v0)); v1 = v1 / (1.f + __expf(-v1));
                    v2 = v2 / (1.f + __expf(-v2)); v3 = v3 / (1.f + __expf(-v3));
                }
                s[i * 2 + 0] += v0 * w0 + v1 * w1;
                s[i * 2 + 1] += v2 * w0 + v3 * w1;
            }
        #pragma unroll
        for (int q = 0; q < 4; ++q) {
            s[q] += __shfl_xor_sync(0xffffffffu, s[q], 1);
            s[q] += __shfl_xor_sync(0xffffffffu, s[q], 2);
        }
        if (t == 0) {
            #pragma unroll
            for (int i = 0; i < 2; ++i) {
                int r0 = m0 + wm + i * 16 + g;
                if (r0 < M)
                    asm volatile("red.global.add.f32 [%0], %1;" :: "l"(Y + r0), "f"(s[i*2]) : "memory");
                if (r0 + 8 < M)
                    asm volatile("red.global.add.f32 [%0], %1;" :: "l"(Y + r0 + 8), "f"(s[i*2+1]) : "memory");
            }
        }
    } else {
        #pragma unroll
        for (int i = 0; i < 2; ++i) {
            int r0 = m0 + wm + i * 16 + g;
            #pragma unroll
            for (int j = 0; j < 8; ++j) {
                int col = n0 + wn + j * 8 + t * 2;
                float b0 = BIAS ? __ldg(bias + col) : 0.f;
                float b1 = BIAS ? __ldg(bias + col + 1) : 0.f;
                float v0 = acc[i][j][0] + b0, v1 = acc[i][j][1] + b1;
                float v2 = acc[i][j][2] + b0, v3 = acc[i][j][3] + b1;
                if (SILU) {
                    v0 = v0 / (1.f + __expf(-v0)); v1 = v1 / (1.f + __expf(-v1));
                    v2 = v2 / (1.f + __expf(-v2)); v3 = v3 / (1.f + __expf(-v3));
                }
                if (r0 < M)
                    *reinterpret_cast<float2*>(Y + (size_t)r0 * D_DIM + col) = make_float2(v0, v1);
                if (r0 + 8 < M)
                    *reinterpret_cast<float2*>(Y + (size_t)(r0 + 8) * D_DIM + col) = make_float2(v2, v3);
            }
        }
    }
}

// ---------------------------------------------------------------------------
// Launch
// Inputs: 0:x[E,128] 1:rbf[E,6] 2:i[E] 3:W_rbf[128,6] 4:W_up[256,128]
//         5:Ws[3,256,256] 6:bs[3,256] 7:W_out[1,256] (8:num_nodes)
// ---------------------------------------------------------------------------
extern "C" void kernel_launch(void* const* d_in, const int* in_sizes, int n_in,
                              void* d_out, int out_size) {
    const float* x     = (const float*)d_in[0];
    const float* rbf   = (const float*)d_in[1];
    const int*   idx   = (const int*)  d_in[2];
    const float* W_rbf = (const float*)d_in[3];
    const float* W_up  = (const float*)d_in[4];
    const float* Ws    = (const float*)d_in[5];
    const float* bs    = (const float*)d_in[6];
    const float* W_out = (const float*)d_in[7];
    float* out = (float*)d_out;

    const int E = in_sizes[2];
    const int M = out_size;

    float *agg, *y0, *y1;
    __half *whi, *wlo;
    cudaGetSymbolAddress((void**)&agg, g_agg);
    cudaGetSymbolAddress((void**)&y0,  g_y0);
    cudaGetSymbolAddress((void**)&y1,  g_y1);
    cudaGetSymbolAddress((void**)&whi, g_whi);
    cudaGetSymbolAddress((void**)&wlo, g_wlo);

    prep_w<<<224, 256>>>(W_up, Ws, whi, wlo);
    zero_kernel<<<1024, 256>>>((float4*)agg, M * H_DIM / 4);
    zero_kernel<<<128, 256>>>((float4*)out, M / 4);

    edge_kernel<<<1184, 256>>>(x, rbf, idx, W_rbf, agg, E);

    const int tiles = (M + 127) / 128;
    dim3 grid(tiles, 2);
    const __half* whi_l = whi + 256 * 128;
    const __half* wlo_l = wlo + 256 * 128;

    // up-projection: y0 = agg @ W_up^T
    gemm_mma<128, false, false, false><<<grid, 256>>>(agg, whi, wlo, nullptr, nullptr, y0, M);
    // layer 0: y1 = silu(y0 @ W0^T + b0)
    gemm_mma<256, true, true, false><<<grid, 256>>>(y0, whi_l + 0*65536, wlo_l + 0*65536, bs + 0*D_DIM, nullptr, y1, M);
    // layer 1: y0 = silu(y1 @ W1^T + b1)
    gemm_mma<256, true, true, false><<<grid, 256>>>(y1, whi_l + 1*65536, wlo_l + 1*65536, bs + 1*D_DIM, nullptr, y0, M);
    // layer 2 + fused projection into out
    gemm_mma<256, true, true, true ><<<grid, 256>>>(y0, whi_l + 2*65536, wlo_l + 2*65536, bs + 2*D_DIM, W_out, out, M);
}

// round 12
// speedup vs baseline: 1.2231x; 1.0989x over previous
#include <cuda_runtime.h>
#include <cuda_fp16.h>
#include <cstdint>
#include <math.h>

#define H_DIM 128
#define R_DIM 6
#define D_DIM 256
#define MAX_NODES 50000

// Scratch
__device__ __align__(128) float g_agg[(size_t)MAX_NODES * H_DIM];   // 25.6 MB
__device__ __align__(128) float g_y0 [(size_t)MAX_NODES * D_DIM];   // 51.2 MB
__device__ __align__(128) float g_y1 [(size_t)MAX_NODES * D_DIM];   // 51.2 MB
// Pre-split weights (fp16 hi/lo): [0,32768) = W_up (256x128), then 3x Ws (256x256)
#define W_TOTAL (256*128 + 3*256*256)
__device__ __align__(128) __half g_whi[W_TOTAL];
__device__ __align__(128) __half g_wlo[W_TOTAL];

__device__ __forceinline__ uint32_t pack_h2(float a, float b) {
    __half2 v = __halves2half2(__float2half_rn(a), __float2half_rn(b));
    return *reinterpret_cast<uint32_t*>(&v);
}

// ---------------------------------------------------------------------------
// Prep kernels
// ---------------------------------------------------------------------------
__global__ void prep_w(const float* __restrict__ W_up, const float* __restrict__ Ws,
                       __half* __restrict__ whi, __half* __restrict__ wlo) {
    int i = blockIdx.x * blockDim.x + threadIdx.x;
    int stride = gridDim.x * blockDim.x;
    for (; i < W_TOTAL; i += stride) {
        float v = (i < 256 * 128) ? W_up[i] : Ws[i - 256 * 128];
        __half h = __float2half_rn(v);
        whi[i] = h;
        wlo[i] = __float2half_rn(v - __half2float(h));
    }
}

__global__ void zero_kernel(float4* __restrict__ p, int n4) {
    int i = blockIdx.x * blockDim.x + threadIdx.x;
    int stride = gridDim.x * blockDim.x;
    float4 z = make_float4(0.f, 0.f, 0.f, 0.f);
    for (; i < n4; i += stride) p[i] = z;
}

// ---------------------------------------------------------------------------
// Edge stage (round-5 proven best: 2 edges/warp-iter, 4ch/lane, red.v4)
// ---------------------------------------------------------------------------
__global__ void edge_kernel(const float* __restrict__ x,
                            const float* __restrict__ rbf,
                            const int*   __restrict__ idx,
                            const float* __restrict__ Wrbf,
                            float*       __restrict__ agg,
                            int E) {
    const int lane = threadIdx.x & 31;
    const int warp = (blockIdx.x * blockDim.x + threadIdx.x) >> 5;
    const int nwarps = (gridDim.x * blockDim.x) >> 5;

    float w[4][6];
    #pragma unroll
    for (int j = 0; j < 4; ++j)
        #pragma unroll
        for (int r = 0; r < R_DIM; ++r)
            w[j][r] = __ldg(Wrbf + (lane * 4 + j) * R_DIM + r);

    for (int e0 = warp * 2; e0 < E; e0 += nwarps * 2) {
        const int e1 = e0 + 1;
        const bool has1 = e1 < E;

        const float2* rp0 = reinterpret_cast<const float2*>(rbf + (size_t)e0 * R_DIM);
        float2 a01 = __ldg(rp0 + 0), a23 = __ldg(rp0 + 1), a45 = __ldg(rp0 + 2);
        int n0 = __ldg(idx + e0);
        float4 xv0 = __ldg(reinterpret_cast<const float4*>(x + (size_t)e0 * H_DIM) + lane);

        float2 b01 = a01, b23 = a23, b45 = a45;
        int n1 = n0;
        float4 xv1 = make_float4(0.f, 0.f, 0.f, 0.f);
        if (has1) {
            const float2* rp1 = reinterpret_cast<const float2*>(rbf + (size_t)e1 * R_DIM);
            b01 = __ldg(rp1 + 0); b23 = __ldg(rp1 + 1); b45 = __ldg(rp1 + 2);
            n1 = __ldg(idx + e1);
            xv1 = __ldg(reinterpret_cast<const float4*>(x + (size_t)e1 * H_DIM) + lane);
        }

        #pragma unroll
        for (int pass = 0; pass < 2; ++pass) {
            float2 r01 = pass ? b01 : a01;
            float2 r23 = pass ? b23 : a23;
            float2 r45 = pass ? b45 : a45;
            float4 xv  = pass ? xv1 : xv0;
            int node   = pass ? n1 : n0;
            if (pass && !has1) break;

            float g0 = w[0][0]*r01.x + w[0][1]*r01.y + w[0][2]*r23.x + w[0][3]*r23.y + w[0][4]*r45.x + w[0][5]*r45.y;
            float g1 = w[1][0]*r01.x + w[1][1]*r01.y + w[1][2]*r23.x + w[1][3]*r23.y + w[1][4]*r45.x + w[1][5]*r45.y;
            float g2 = w[2][0]*r01.x + w[2][1]*r01.y + w[2][2]*r23.x + w[2][3]*r23.y + w[2][4]*r45.x + w[2][5]*r45.y;
            float g3 = w[3][0]*r01.x + w[3][1]*r01.y + w[3][2]*r23.x + w[3][3]*r23.y + w[3][4]*r45.x + w[3][5]*r45.y;

            float vx = g0 * xv.x, vy = g1 * xv.y, vz = g2 * xv.z, vw = g3 * xv.w;
            float* dst = agg + (size_t)node * H_DIM + lane * 4;
            asm volatile("red.global.add.v4.f32 [%0], {%1, %2, %3, %4};"
                         :: "l"(dst), "f"(vx), "f"(vy), "f"(vz), "f"(vw) : "memory");
        }
    }
}

// ---------------------------------------------------------------------------
// fp16-split GEMM (3 products, f32 acc), K-chunk 64, dynamic SMEM (72KB),
// coalesced fills. CTA tile 128(m) x 128(n), 8 warps of 32x64.
// ---------------------------------------------------------------------------
#define STRIDE_H 72            // halfwords per SMEM row (64 data + 8 pad)
#define ARR_HW   (128 * STRIDE_H)          // 9216 halfwords per array
#define SMEM_BYTES (4 * ARR_HW * 2)        // 73728 bytes

__device__ __forceinline__ void mma_f16(float* d, const uint32_t* a, uint32_t b0, uint32_t b1) {
    asm("mma.sync.aligned.m16n8k16.row.col.f32.f16.f16.f32 "
        "{%0,%1,%2,%3}, {%4,%5,%6,%7}, {%8,%9}, {%0,%1,%2,%3};"
        : "+f"(d[0]), "+f"(d[1]), "+f"(d[2]), "+f"(d[3])
        : "r"(a[0]), "r"(a[1]), "r"(a[2]), "r"(a[3]), "r"(b0), "r"(b1));
}

template<int K_TOTAL, bool BIAS, bool SILU, bool PROJ>
__global__ void __launch_bounds__(256, 2)
gemm_mma(const float* __restrict__ A,
         const __half* __restrict__ Bhi,
         const __half* __restrict__ Blo,
         const float* __restrict__ bias,
         const float* __restrict__ wout,
         float* __restrict__ Y,
         int M) {
    extern __shared__ __align__(16) uint16_t sm[];
    uint16_t* sAhi = sm;
    uint16_t* sAlo = sm + ARR_HW;
    uint16_t* sBhi = sm + 2 * ARR_HW;
    uint16_t* sBlo = sm + 3 * ARR_HW;

    const int tid  = threadIdx.x;
    const int wid  = tid >> 5, lane = tid & 31;
    const int g    = lane >> 2, t = lane & 3;
    const int m0   = blockIdx.x * 128;
    const int n0   = blockIdx.y * 128;
    const int wm   = (wid & 3) * 32;
    const int wn   = (wid >> 2) * 64;

    float acc[2][8][4];
    #pragma unroll
    for (int i = 0; i < 2; ++i)
        #pragma unroll
        for (int j = 0; j < 8; ++j)
            #pragma unroll
            for (int q = 0; q < 4; ++q) acc[i][j][q] = 0.f;

    const uint32_t* A32hi = reinterpret_cast<const uint32_t*>(sAhi);
    const uint32_t* A32lo = reinterpret_cast<const uint32_t*>(sAlo);
    const uint32_t* B32hi = reinterpret_cast<const uint32_t*>(sBhi);
    const uint32_t* B32lo = reinterpret_cast<const uint32_t*>(sBlo);

    // A fill: 16 threads/row (1 float4 each), 16 rows/pass, 8 passes
    const int a_seg = tid & 15;
    const int a_rip = tid >> 4;
    // B fill: 8 threads/row (1 uint4 = 8 halves each), 32 rows/pass, 4 passes
    const int b_seg = tid & 7;
    const int b_rip = tid >> 3;

    for (int c = 0; c < K_TOTAL / 64; ++c) {
        // ---- fill A (fp32 -> fp16 hi/lo), coalesced ----
        #pragma unroll
        for (int p = 0; p < 8; ++p) {
            const int row = p * 16 + a_rip;
            const int grow = m0 + row;
            float4 f = make_float4(0.f, 0.f, 0.f, 0.f);
            if (grow < M)
                f = *reinterpret_cast<const float4*>(A + (size_t)grow * K_TOTAL + c * 64 + a_seg * 4);
            uint2 Hv, Lv;
            Hv.x = pack_h2(f.x, f.y);
            Hv.y = pack_h2(f.z, f.w);
            Lv.x = pack_h2(f.x - __half2float(__float2half_rn(f.x)),
                           f.y - __half2float(__float2half_rn(f.y)));
            Lv.y = pack_h2(f.z - __half2float(__float2half_rn(f.z)),
                           f.w - __half2float(__float2half_rn(f.w)));
            const int hw = row * STRIDE_H + a_seg * 4;
            *reinterpret_cast<uint2*>(sAhi + hw) = Hv;
            *reinterpret_cast<uint2*>(sAlo + hw) = Lv;
        }
        // ---- fill B, coalesced ----
        #pragma unroll
        for (int p = 0; p < 4; ++p) {
            const int row = p * 32 + b_rip;
            const size_t off = (size_t)(n0 + row) * K_TOTAL + c * 64 + b_seg * 8;
            uint4 bh = *reinterpret_cast<const uint4*>(Bhi + off);
            uint4 bl = *reinterpret_cast<const uint4*>(Blo + off);
            const int hw = row * STRIDE_H + b_seg * 8;
            *reinterpret_cast<uint4*>(sBhi + hw) = bh;
            *reinterpret_cast<uint4*>(sBlo + hw) = bl;
        }
        __syncthreads();

        // ---- compute: 4 k16-steps x 3 products ----
        #pragma unroll
        for (int ks = 0; ks < 4; ++ks) {
            const int kw = ks * 8;
            uint32_t ahi[2][4], alo[2][4];
            #pragma unroll
            for (int i = 0; i < 2; ++i) {
                int r0 = (wm + i * 16 + g) * (STRIDE_H / 2) + kw + t;
                ahi[i][0] = A32hi[r0];        ahi[i][1] = A32hi[r0 + 8 * (STRIDE_H / 2)];
                ahi[i][2] = A32hi[r0 + 4];    ahi[i][3] = A32hi[r0 + 8 * (STRIDE_H / 2) + 4];
                alo[i][0] = A32lo[r0];        alo[i][1] = A32lo[r0 + 8 * (STRIDE_H / 2)];
                alo[i][2] = A32lo[r0 + 4];    alo[i][3] = A32lo[r0 + 8 * (STRIDE_H / 2) + 4];
            }
            #pragma unroll
            for (int j = 0; j < 8; ++j) {
                int nb = (wn + j * 8 + g) * (STRIDE_H / 2) + kw + t;
                uint32_t bh0 = B32hi[nb], bh1 = B32hi[nb + 4];
                uint32_t bl0 = B32lo[nb], bl1 = B32lo[nb + 4];
                #pragma unroll
                for (int i = 0; i < 2; ++i) {
                    mma_f16(acc[i][j], ahi[i], bh0, bh1);
                    mma_f16(acc[i][j], ahi[i], bl0, bl1);
                    mma_f16(acc[i][j], alo[i], bh0, bh1);
                }
            }
        }
        __syncthreads();
    }

    // ---- epilogue ----
    if (PROJ) {
        float s[4] = {0.f, 0.f, 0.f, 0.f};
        #pragma unroll
        for (int i = 0; i < 2; ++i)
            #pragma unroll
            for (int j = 0; j < 8; ++j) {
                int col = n0 + wn + j * 8 + t * 2;
                float w0 = __ldg(wout + col), w1 = __ldg(wout + col + 1);
                float b0 = BIAS ? __ldg(bias + col) : 0.f;
                float b1 = BIAS ? __ldg(bias + col + 1) : 0.f;
                float v0 = acc[i][j][0] + b0, v1 = acc[i][j][1] + b1;
                float v2 = acc[i][j][2] + b0, v3 = acc[i][j][3] + b1;
                if (SILU) {
                    v0 = v0 / (1.f + __expf(-v0)); v1 = v1 / (1.f + __expf(-v1));
                    v2 = v2 / (1.f + __expf(-v2)); v3 = v3 / (1.f + __expf(-v3));
                }
                s[i * 2 + 0] += v0 * w0 + v1 * w1;
                s[i * 2 + 1] += v2 * w0 + v3 * w1;
            }
        #pragma unroll
        for (int q = 0; q < 4; ++q) {
            s[q] += __shfl_xor_sync(0xffffffffu, s[q], 1);
            s[q] += __shfl_xor_sync(0xffffffffu, s[q], 2);
        }
        if (t == 0) {
            #pragma unroll
            for (int i = 0; i < 2; ++i) {
                int r0 = m0 + wm + i * 16 + g;
                if (r0 < M)
                    asm volatile("red.global.add.f32 [%0], %1;" :: "l"(Y + r0), "f"(s[i*2]) : "memory");
                if (r0 + 8 < M)
                    asm volatile("red.global.add.f32 [%0], %1;" :: "l"(Y + r0 + 8), "f"(s[i*2+1]) : "memory");
            }
        }
    } else {
        #pragma unroll
        for (int i = 0; i < 2; ++i) {
            int r0 = m0 + wm + i * 16 + g;
            #pragma unroll
            for (int j = 0; j < 8; ++j) {
                int col = n0 + wn + j * 8 + t * 2;
                float b0 = BIAS ? __ldg(bias + col) : 0.f;
                float b1 = BIAS ? __ldg(bias + col + 1) : 0.f;
                float v0 = acc[i][j][0] + b0, v1 = acc[i][j][1] + b1;
                float v2 = acc[i][j][2] + b0, v3 = acc[i][j][3] + b1;
                if (SILU) {
                    v0 = v0 / (1.f + __expf(-v0)); v1 = v1 / (1.f + __expf(-v1));
                    v2 = v2 / (1.f + __expf(-v2)); v3 = v3 / (1.f + __expf(-v3));
                }
                if (r0 < M)
                    *reinterpret_cast<float2*>(Y + (size_t)r0 * D_DIM + col) = make_float2(v0, v1);
                if (r0 + 8 < M)
                    *reinterpret_cast<float2*>(Y + (size_t)(r0 + 8) * D_DIM + col) = make_float2(v2, v3);
            }
        }
    }
}

// ---------------------------------------------------------------------------
// Launch
// Inputs: 0:x[E,128] 1:rbf[E,6] 2:i[E] 3:W_rbf[128,6] 4:W_up[256,128]
//         5:Ws[3,256,256] 6:bs[3,256] 7:W_out[1,256] (8:num_nodes)
// ---------------------------------------------------------------------------
extern "C" void kernel_launch(void* const* d_in, const int* in_sizes, int n_in,
                              void* d_out, int out_size) {
    const float* x     = (const float*)d_in[0];
    const float* rbf   = (const float*)d_in[1];
    const int*   idx   = (const int*)  d_in[2];
    const float* W_rbf = (const float*)d_in[3];
    const float* W_up  = (const float*)d_in[4];
    const float* Ws    = (const float*)d_in[5];
    const float* bs    = (const float*)d_in[6];
    const float* W_out = (const float*)d_in[7];
    float* out = (float*)d_out;

    const int E = in_sizes[2];
    const int M = out_size;

    float *agg, *y0, *y1;
    __half *whi, *wlo;
    cudaGetSymbolAddress((void**)&agg, g_agg);
    cudaGetSymbolAddress((void**)&y0,  g_y0);
    cudaGetSymbolAddress((void**)&y1,  g_y1);
    cudaGetSymbolAddress((void**)&whi, g_whi);
    cudaGetSymbolAddress((void**)&wlo, g_wlo);

    cudaFuncSetAttribute(gemm_mma<128, false, false, false>, cudaFuncAttributeMaxDynamicSharedMemorySize, SMEM_BYTES);
    cudaFuncSetAttribute(gemm_mma<256, true,  true,  false>, cudaFuncAttributeMaxDynamicSharedMemorySize, SMEM_BYTES);
    cudaFuncSetAttribute(gemm_mma<256, true,  true,  true >, cudaFuncAttributeMaxDynamicSharedMemorySize, SMEM_BYTES);

    prep_w<<<224, 256>>>(W_up, Ws, whi, wlo);
    zero_kernel<<<1024, 256>>>((float4*)agg, M * H_DIM / 4);
    zero_kernel<<<128, 256>>>((float4*)out, M / 4);

    edge_kernel<<<1184, 256>>>(x, rbf, idx, W_rbf, agg, E);

    const int tiles = (M + 127) / 128;
    dim3 grid(tiles, 2);
    const __half* whi_l = whi + 256 * 128;
    const __half* wlo_l = wlo + 256 * 128;

    // up-projection: y0 = agg @ W_up^T
    gemm_mma<128, false, false, false><<<grid, 256, SMEM_BYTES>>>(agg, whi, wlo, nullptr, nullptr, y0, M);
    // layer 0: y1 = silu(y0 @ W0^T + b0)
    gemm_mma<256, true, true, false><<<grid, 256, SMEM_BYTES>>>(y0, whi_l + 0*65536, wlo_l + 0*65536, bs + 0*D_DIM, nullptr, y1, M);
    // layer 1: y0 = silu(y1 @ W1^T + b1)
    gemm_mma<256, true, true, false><<<grid, 256, SMEM_BYTES>>>(y1, whi_l + 1*65536, wlo_l + 1*65536, bs + 1*D_DIM, nullptr, y0, M);
    // layer 2 + fused projection into out
    gemm_mma<256, true, true, true ><<<grid, 256, SMEM_BYTES>>>(y0, whi_l + 2*65536, wlo_l + 2*65536, bs + 2*D_DIM, W_out, out, M);
}